// round 14
// baseline (speedup 1.0000x reference)
#include <cuda_runtime.h>
#include <cuda_bf16.h>

// Problem constants (fixed by setup_inputs)
#define CH    16
#define HH    512
#define WW    512
#define KS    7
#define RAD   3
#define DIL   2
#define PAD   6            // RAD*DIL
#define DYN   3            // output channels

// Tiling: 32 x 52 pixels per block, 832 threads, 2 pixels per thread, 1 block/SM
#define TW    32
#define TPH   52
#define LW    (TW + 2*PAD)   // 44
#define LH    (TPH + 2*PAD)  // 64
#define PLANE (LW*LH)        // 2816
#define NTHREADS 832
#define NPAIR 8              // channel pairs
#define NQUAD 4              // channel quads

#define SMEM_BYTES (17 * PLANE * 4)   // 16 channel planes + s2 plane = 191488 B

#define LOG2E 1.4426950408889634f

typedef unsigned long long u64;

__device__ __forceinline__ u64 pk2(float lo, float hi) {
    u64 r; asm("mov.b64 %0,{%1,%2};" : "=l"(r) : "f"(lo), "f"(hi)); return r;
}
__device__ __forceinline__ void upk2(u64 v, float& lo, float& hi) {
    asm("mov.b64 {%0,%1},%2;" : "=f"(lo), "=f"(hi) : "l"(v));
}
__device__ __forceinline__ u64 ffma2(u64 a, u64 b, u64 c) {
    u64 d; asm("fma.rn.f32x2 %0,%1,%2,%3;" : "=l"(d) : "l"(a), "l"(b), "l"(c)); return d;
}
__device__ __forceinline__ u64 fadd2(u64 a, u64 b) {
    u64 d; asm("add.rn.f32x2 %0,%1,%2;" : "=l"(d) : "l"(a), "l"(b)); return d;
}
__device__ __forceinline__ u64 fmul2(u64 a, u64 b) {
    u64 d; asm("mul.rn.f32x2 %0,%1,%2;" : "=l"(d) : "l"(a), "l"(b)); return d;
}
__device__ __forceinline__ float ex2(float x) {
    float r; asm("ex2.approx.f32 %0,%1;" : "=f"(r) : "f"(x)); return r;
}

// One tap row (padded row = lr0 + 2*IROW) for the subset of the 2 pixels given
// by literal flags D0/D1 (dead chains removed at compile time).
#define TAP_ROW(IROW, D0, D1, B0, B1)                                          \
do {                                                                           \
    const int rowoff_ = (lr0 + 2 * (IROW)) * LW + tx;                          \
    _Pragma("unroll")                                                          \
    for (int j = 0; j < KS; j++) {                                             \
        const int p_ = rowoff_ + 2 * j;                                        \
        const float t_ = s2t[p_] + sxj[j];                                     \
        const ulonglong2 va = Tq[0 * PLANE + p_];                              \
        const ulonglong2 vb = Tq[1 * PLANE + p_];                              \
        const ulonglong2 vc = Tq[2 * PLANE + p_];                              \
        const ulonglong2 vd = Tq[3 * PLANE + p_];                              \
        float x0_, x1_, x2_, x3d_;                                             \
        upk2(va.x, x0_, x1_);                                                  \
        upk2(va.y, x2_, x3d_);                                                 \
        if (D0) {                                                              \
            u64 A0 = fmul2(y0p[0], va.x);                                      \
            u64 A1 = fmul2(y0p[1], va.y);                                      \
            A0 = ffma2(y0p[2], vb.x, A0);  A1 = ffma2(y0p[3], vb.y, A1);       \
            A0 = ffma2(y0p[4], vc.x, A0);  A1 = ffma2(y0p[5], vc.y, A1);       \
            A0 = ffma2(y0p[6], vd.x, A0);  A1 = ffma2(y0p[7], vd.y, A1);       \
            u64 SA = fadd2(A0, A1);                                            \
            float sl_, sh_;  upk2(SA, sl_, sh_);                               \
            const float w0_ = ex2((sl_ + sh_) + (t_ + (B0)));                  \
            n00 = fmaf(w0_, x0_, n00);                                         \
            n01 = fmaf(w0_, x1_, n01);                                         \
            n02 = fmaf(w0_, x2_, n02);                                         \
            d0 += w0_;                                                         \
        }                                                                      \
        if (D1) {                                                              \
            u64 B0c = fmul2(y1p[0], va.x);                                     \
            u64 B1c = fmul2(y1p[1], va.y);                                     \
            B0c = ffma2(y1p[2], vb.x, B0c);  B1c = ffma2(y1p[3], vb.y, B1c);   \
            B0c = ffma2(y1p[4], vc.x, B0c);  B1c = ffma2(y1p[5], vc.y, B1c);   \
            B0c = ffma2(y1p[6], vd.x, B0c);  B1c = ffma2(y1p[7], vd.y, B1c);   \
            u64 SB = fadd2(B0c, B1c);                                          \
            float sl_, sh_;  upk2(SB, sl_, sh_);                               \
            const float w1_ = ex2((sl_ + sh_) + (t_ + (B1)));                  \
            n10 = fmaf(w1_, x0_, n10);                                         \
            n11 = fmaf(w1_, x1_, n11);                                         \
            n12 = fmaf(w1_, x2_, n12);                                         \
            d1 += w1_;                                                         \
        }                                                                      \
    }                                                                          \
} while (0)

__global__ __launch_bounds__(NTHREADS, 1)
void bilateral_kernel(const float* __restrict__ in,
                      const float* __restrict__ prm,
                      float* __restrict__ out)
{
    extern __shared__ float smf[];
    // Quad-interleaved tile: ulonglong2 view [NQUAD][PLANE]; quad q holds ch 4q..4q+3
    ulonglong2* Tq  = (ulonglong2*)smf;
    float*      s2t = smf + CH * PLANE;     // [LH][LW], -1e30 marks OOB pixels

    const int tx  = threadIdx.x;         // 0..31
    const int ty  = threadIdx.y;         // 0..25
    const int tid = ty * TW + tx;
    const int bx0 = blockIdx.x * TW;
    const int by0 = blockIdx.y * TPH;
    const int b   = blockIdx.z;

    // Coefficients pre-scaled by log2(e) -> raw ex2
    float rcl[CH];
    #pragma unroll
    for (int c = 0; c < CH; c++) rcl[c] = __ldg(&prm[c]) * LOG2E;
    const float sxl = __ldg(&prm[CH]) * LOG2E;
    const float syl = __ldg(&prm[CH + 1]) * LOG2E;

    const float* inb = in + (size_t)b * CH * HH * WW;

    // ---- Phase 1: load haloed tile into quad-interleaved smem (zero-fill OOB) ----
    for (int idx = tid; idx < CH * PLANE; idx += NTHREADS) {
        int q    = idx / (4 * PLANE);
        int rem  = idx - q * (4 * PLANE);
        int p    = rem >> 2;
        int c    = 4 * q + (rem & 3);
        int lr = p / LW;
        int lc = p - lr * LW;
        int gy = by0 + lr - PAD;
        int gx = bx0 + lc - PAD;
        float v = 0.0f;
        if ((unsigned)gy < (unsigned)HH && (unsigned)gx < (unsigned)WW)
            v = __ldg(&inb[(size_t)c * HH * WW + (size_t)gy * WW + gx]);
        smf[idx] = v;
    }
    __syncthreads();

    // ---- Phase 2: s2'(q) = log2e * sum_c rc_c * x_c(q)^2 ; -1e30 where OOB ----
    for (int p = tid; p < PLANE; p += NTHREADS) {
        int lr = p / LW;
        int lc = p - lr * LW;
        int gy = by0 + lr - PAD;
        int gx = bx0 + lc - PAD;
        float s = -1e30f;
        if ((unsigned)gy < (unsigned)HH && (unsigned)gx < (unsigned)WW) {
            float a0 = 0.f, a1 = 0.f, a2 = 0.f, a3 = 0.f;
            #pragma unroll
            for (int q = 0; q < NQUAD; q++) {
                ulonglong2 v = Tq[q * PLANE + p];
                float x0, x1, x2, x3;
                upk2(v.x, x0, x1);
                upk2(v.y, x2, x3);
                a0 = fmaf(rcl[4*q + 0] * x0, x0, a0);
                a1 = fmaf(rcl[4*q + 1] * x1, x1, a1);
                a2 = fmaf(rcl[4*q + 2] * x2, x2, a2);
                a3 = fmaf(rcl[4*q + 3] * x3, x3, a3);
            }
            s = (a0 + a1) + (a2 + a3);
        }
        s2t[p] = s;
    }
    __syncthreads();

    // ---- Phase 3: two pixels per thread (rows lr0, lr0+2 share tap rows) ----
    // ty 0..25 -> lr0 = 4*(ty>>1)+(ty&1) in {0,1,4,5,...,48,49};
    // pairs {lr0, lr0+2} tile rows 0..51.
    const int lr0 = 4 * (ty >> 1) + (ty & 1);
    const int cp0 = (lr0 + PAD) * LW + (tx + PAD);
    const int cp1 = cp0 + 2 * LW;

    u64 rcn2[NPAIR];
    #pragma unroll
    for (int k = 0; k < NPAIR; k++)
        rcn2[k] = pk2(-2.0f * rcl[2*k], -2.0f * rcl[2*k + 1]);

    u64 y0p[NPAIR], y1p[NPAIR];
    #pragma unroll
    for (int q = 0; q < NQUAD; q++) {
        ulonglong2 v0 = Tq[q * PLANE + cp0];
        ulonglong2 v1 = Tq[q * PLANE + cp1];
        y0p[2*q]   = fmul2(rcn2[2*q],   v0.x);
        y0p[2*q+1] = fmul2(rcn2[2*q+1], v0.y);
        y1p[2*q]   = fmul2(rcn2[2*q],   v1.x);
        y1p[2*q+1] = fmul2(rcn2[2*q+1], v1.y);
    }
    const float s2p0 = s2t[cp0];
    const float s2p1 = s2t[cp1];

    float sxj[KS];
    #pragma unroll
    for (int j = 0; j < KS; j++) {
        float dxf = (float)((j - RAD) * DIL);
        sxj[j] = sxl * dxf * dxf;
    }

    float n00 = 0.f, n01 = 0.f, n02 = 0.f, d0 = 0.f;
    float n10 = 0.f, n11 = 0.f, n12 = 0.f, d1 = 0.f;

    // Row validity: px0 i in [0,6] (dy0=2i-6); px1 i in [1,7] (dy1=2i-8).
    // Peeled edge rows compute ONLY the valid pixel chain (no masked waste).
    TAP_ROW(0, 1, 0, fmaf(syl * 6.0f, 6.0f, s2p0), 0.0f);

    #pragma unroll 1
    for (int i = 1; i <= 6; i++) {
        const float dy0 = (float)(2 * i - 6);
        const float dy1 = (float)(2 * i - 8);
        const float base0 = fmaf(syl * dy0, dy0, s2p0);
        const float base1 = fmaf(syl * dy1, dy1, s2p1);
        TAP_ROW(i, 1, 1, base0, base1);
    }

    TAP_ROW(7, 0, 1, 0.0f, fmaf(syl * 6.0f, 6.0f, s2p1));

    const float inv0 = __fdividef(1.0f, d0);   // den >= 1 (center tap w=1)
    const float inv1 = __fdividef(1.0f, d1);
    const int gy0 = by0 + lr0;
    const int gy1 = gy0 + 2;
    const int gx  = bx0 + tx;
    const size_t CS = (size_t)HH * WW;
    const size_t ob = (size_t)b * DYN * CS + gx;
    if (gy0 < HH) {
        size_t o = ob + (size_t)gy0 * WW;
        out[o]          = n00 * inv0;
        out[o + CS]     = n01 * inv0;
        out[o + 2 * CS] = n02 * inv0;
    }
    if (gy1 < HH) {
        size_t o = ob + (size_t)gy1 * WW;
        out[o]          = n10 * inv1;
        out[o + CS]     = n11 * inv1;
        out[o + 2 * CS] = n12 * inv1;
    }
}

extern "C" void kernel_launch(void* const* d_in, const int* in_sizes, int n_in,
                              void* d_out, int out_size)
{
    const float* in  = (const float*)d_in[0];
    const float* prm = (const float*)d_in[1];
    float*       out = (float*)d_out;

    const int B = in_sizes[0] / (CH * HH * WW);   // = 4

    cudaFuncSetAttribute(bilateral_kernel,
                         cudaFuncAttributeMaxDynamicSharedMemorySize,
                         (int)SMEM_BYTES);

    dim3 block(TW, 26, 1);                             // 832 threads
    dim3 grid(WW / TW, (HH + TPH - 1) / TPH, B);       // 16 x 10 x 4
    bilateral_kernel<<<grid, block, SMEM_BYTES>>>(in, prm, out);
}

// round 16
// speedup vs baseline: 1.1327x; 1.1327x over previous
#include <cuda_runtime.h>
#include <cuda_bf16.h>

// Problem constants (fixed by setup_inputs)
#define CH    16
#define HH    512
#define WW    512
#define KS    7
#define RAD   3
#define DIL   2
#define PAD   6            // RAD*DIL
#define DYN   3            // output channels

// Tiling: 32 x 24 pixels per block, 384 threads, 2 pixels per thread
#define TW    32
#define TPH   24
#define LW    (TW + 2*PAD)   // 44
#define LH    (TPH + 2*PAD)  // 36
#define PLANE (LW*LH)        // 1584
#define NTHREADS 384
#define NPAIR 8              // channel pairs
#define NQUAD 4              // channel quads

#define SMEM_BYTES (17 * PLANE * 4)   // 16 channel planes + s2 plane = 107712 B

#define LOG2E 1.4426950408889634f

typedef unsigned long long u64;

__device__ __forceinline__ u64 pk2(float lo, float hi) {
    u64 r; asm("mov.b64 %0,{%1,%2};" : "=l"(r) : "f"(lo), "f"(hi)); return r;
}
__device__ __forceinline__ void upk2(u64 v, float& lo, float& hi) {
    asm("mov.b64 {%0,%1},%2;" : "=f"(lo), "=f"(hi) : "l"(v));
}
__device__ __forceinline__ u64 ffma2(u64 a, u64 b, u64 c) {
    u64 d; asm("fma.rn.f32x2 %0,%1,%2,%3;" : "=l"(d) : "l"(a), "l"(b), "l"(c)); return d;
}
__device__ __forceinline__ u64 fadd2(u64 a, u64 b) {
    u64 d; asm("add.rn.f32x2 %0,%1,%2;" : "=l"(d) : "l"(a), "l"(b)); return d;
}
__device__ __forceinline__ u64 fmul2(u64 a, u64 b) {
    u64 d; asm("mul.rn.f32x2 %0,%1,%2;" : "=l"(d) : "l"(a), "l"(b)); return d;
}
__device__ __forceinline__ float ex2(float x) {
    float r; asm("ex2.approx.f32 %0,%1;" : "=f"(r) : "f"(x)); return r;
}

// One tap row (padded row = lr0 + 2*IROW) for the subset of the 2 pixels given
// by literal flags D0/D1 (dead chains removed at compile time).
// sxj table replaced by literal constants: sx_c(j) = (2j-6)^2, folded via FFMA.
#define TAP_ROW(IROW, D0, D1, B0, B1)                                          \
do {                                                                           \
    const int rowoff_ = (lr0 + 2 * (IROW)) * LW + tx;                          \
    _Pragma("unroll")                                                          \
    for (int j = 0; j < KS; j++) {                                             \
        const int p_ = rowoff_ + 2 * j;                                        \
        const float dxc_ = (float)((2 * j - 6) * (2 * j - 6));                 \
        const float t_ = fmaf(sxl, dxc_, s2t[p_]);                             \
        const ulonglong2 va = Tq[0 * PLANE + p_];                              \
        const ulonglong2 vb = Tq[1 * PLANE + p_];                              \
        const ulonglong2 vc = Tq[2 * PLANE + p_];                              \
        const ulonglong2 vd = Tq[3 * PLANE + p_];                              \
        float x0_, x1_, x2_, x3d_;                                             \
        upk2(va.x, x0_, x1_);                                                  \
        upk2(va.y, x2_, x3d_);                                                 \
        if (D0) {                                                              \
            u64 A0 = fmul2(y0p[0], va.x);                                      \
            u64 A1 = fmul2(y0p[1], va.y);                                      \
            A0 = ffma2(y0p[2], vb.x, A0);  A1 = ffma2(y0p[3], vb.y, A1);       \
            A0 = ffma2(y0p[4], vc.x, A0);  A1 = ffma2(y0p[5], vc.y, A1);       \
            A0 = ffma2(y0p[6], vd.x, A0);  A1 = ffma2(y0p[7], vd.y, A1);       \
            u64 SA = fadd2(A0, A1);                                            \
            float sl_, sh_;  upk2(SA, sl_, sh_);                               \
            const float w0_ = ex2((sl_ + sh_) + (t_ + (B0)));                  \
            n00 = fmaf(w0_, x0_, n00);                                         \
            n01 = fmaf(w0_, x1_, n01);                                         \
            n02 = fmaf(w0_, x2_, n02);                                         \
            d0 += w0_;                                                         \
        }                                                                      \
        if (D1) {                                                              \
            u64 B0c = fmul2(y1p[0], va.x);                                     \
            u64 B1c = fmul2(y1p[1], va.y);                                     \
            B0c = ffma2(y1p[2], vb.x, B0c);  B1c = ffma2(y1p[3], vb.y, B1c);   \
            B0c = ffma2(y1p[4], vc.x, B0c);  B1c = ffma2(y1p[5], vc.y, B1c);   \
            B0c = ffma2(y1p[6], vd.x, B0c);  B1c = ffma2(y1p[7], vd.y, B1c);   \
            u64 SB = fadd2(B0c, B1c);                                          \
            float sl_, sh_;  upk2(SB, sl_, sh_);                               \
            const float w1_ = ex2((sl_ + sh_) + (t_ + (B1)));                  \
            n10 = fmaf(w1_, x0_, n10);                                         \
            n11 = fmaf(w1_, x1_, n11);                                         \
            n12 = fmaf(w1_, x2_, n12);                                         \
            d1 += w1_;                                                         \
        }                                                                      \
    }                                                                          \
} while (0)

__global__ __launch_bounds__(NTHREADS, 2)
void bilateral_kernel(const float* __restrict__ in,
                      const float* __restrict__ prm,
                      float* __restrict__ out)
{
    extern __shared__ float smf[];
    // Quad-interleaved tile: ulonglong2 view [NQUAD][PLANE]; quad q holds ch 4q..4q+3
    ulonglong2* Tq  = (ulonglong2*)smf;
    float*      s2t = smf + CH * PLANE;     // [LH][LW], -1e30 marks OOB pixels

    const int tx  = threadIdx.x;         // 0..31
    const int ty  = threadIdx.y;         // 0..11
    const int tid = ty * TW + tx;
    const int bx0 = blockIdx.x * TW;
    // Clamped overlap mapping: last y-block covers rows 488..511 (overlap rows
    // recomputed identically by two blocks; writes are byte-identical).
    int by0 = blockIdx.y * TPH;
    if (by0 > HH - TPH) by0 = HH - TPH;
    const int b   = blockIdx.z;

    // Coefficients pre-scaled by log2(e) -> raw ex2
    float rcl[CH];
    #pragma unroll
    for (int c = 0; c < CH; c++) rcl[c] = __ldg(&prm[c]) * LOG2E;
    const float sxl = __ldg(&prm[CH]) * LOG2E;
    const float syl = __ldg(&prm[CH + 1]) * LOG2E;

    const float* inb = in + (size_t)b * CH * HH * WW;

    // ---- Phase 1: load haloed tile into quad-interleaved smem (zero-fill OOB) ----
    for (int idx = tid; idx < CH * PLANE; idx += NTHREADS) {
        int q    = idx / (4 * PLANE);
        int rem  = idx - q * (4 * PLANE);
        int p    = rem >> 2;
        int c    = 4 * q + (rem & 3);
        int lr = p / LW;
        int lc = p - lr * LW;
        int gy = by0 + lr - PAD;
        int gx = bx0 + lc - PAD;
        float v = 0.0f;
        if ((unsigned)gy < (unsigned)HH && (unsigned)gx < (unsigned)WW)
            v = __ldg(&inb[(size_t)c * HH * WW + (size_t)gy * WW + gx]);
        smf[idx] = v;
    }
    __syncthreads();

    // ---- Phase 2: s2'(q) = log2e * sum_c rc_c * x_c(q)^2 ; -1e30 where OOB ----
    for (int p = tid; p < PLANE; p += NTHREADS) {
        int lr = p / LW;
        int lc = p - lr * LW;
        int gy = by0 + lr - PAD;
        int gx = bx0 + lc - PAD;
        float s = -1e30f;
        if ((unsigned)gy < (unsigned)HH && (unsigned)gx < (unsigned)WW) {
            float a0 = 0.f, a1 = 0.f, a2 = 0.f, a3 = 0.f;
            #pragma unroll
            for (int q = 0; q < NQUAD; q++) {
                ulonglong2 v = Tq[q * PLANE + p];
                float x0, x1, x2, x3;
                upk2(v.x, x0, x1);
                upk2(v.y, x2, x3);
                a0 = fmaf(rcl[4*q + 0] * x0, x0, a0);
                a1 = fmaf(rcl[4*q + 1] * x1, x1, a1);
                a2 = fmaf(rcl[4*q + 2] * x2, x2, a2);
                a3 = fmaf(rcl[4*q + 3] * x3, x3, a3);
            }
            s = (a0 + a1) + (a2 + a3);
        }
        s2t[p] = s;
    }
    __syncthreads();

    // ---- Phase 3: two pixels per thread (rows lr0, lr0+2 share tap rows) ----
    // ty 0..11 -> lr0 = 4*(ty>>1)+(ty&1) in {0,1,4,5,8,9,12,13,16,17,20,21};
    // pairs {lr0, lr0+2} tile rows 0..23. With clamped by0, all outputs in-bounds.
    const int lr0 = 4 * (ty >> 1) + (ty & 1);
    const int cp0 = (lr0 + PAD) * LW + (tx + PAD);
    const int cp1 = cp0 + 2 * LW;

    u64 y0p[NPAIR], y1p[NPAIR];
    #pragma unroll
    for (int q = 0; q < NQUAD; q++) {
        const u64 rl = pk2(-2.0f * rcl[4*q + 0], -2.0f * rcl[4*q + 1]);
        const u64 rh = pk2(-2.0f * rcl[4*q + 2], -2.0f * rcl[4*q + 3]);
        ulonglong2 v0 = Tq[q * PLANE + cp0];
        ulonglong2 v1 = Tq[q * PLANE + cp1];
        y0p[2*q]   = fmul2(rl, v0.x);
        y0p[2*q+1] = fmul2(rh, v0.y);
        y1p[2*q]   = fmul2(rl, v1.x);
        y1p[2*q+1] = fmul2(rh, v1.y);
    }
    const float s2p0 = s2t[cp0];
    const float s2p1 = s2t[cp1];

    float n00 = 0.f, n01 = 0.f, n02 = 0.f, d0 = 0.f;
    float n10 = 0.f, n11 = 0.f, n12 = 0.f, d1 = 0.f;

    // Row validity: px0 i in [0,6] (dy0=2i-6); px1 i in [1,7] (dy1=2i-8).
    // Peeled edge rows compute ONLY the valid pixel chain (no masked waste).
    TAP_ROW(0, 1, 0, fmaf(syl, 36.0f, s2p0), 0.0f);

    #pragma unroll 1
    for (int i = 1; i <= 6; i++) {
        const float dy0 = (float)(2 * i - 6);
        const float dy1 = (float)(2 * i - 8);
        const float base0 = fmaf(syl * dy0, dy0, s2p0);
        const float base1 = fmaf(syl * dy1, dy1, s2p1);
        TAP_ROW(i, 1, 1, base0, base1);
    }

    TAP_ROW(7, 0, 1, 0.0f, fmaf(syl, 36.0f, s2p1));

    const float inv0 = __fdividef(1.0f, d0);   // den >= 1 (center tap w=1)
    const float inv1 = __fdividef(1.0f, d1);
    const int gy0 = by0 + lr0;
    const int gy1 = gy0 + 2;
    const int gx  = bx0 + tx;
    const size_t CS = (size_t)HH * WW;
    const size_t ob = (size_t)b * DYN * CS + gx;
    {
        size_t o = ob + (size_t)gy0 * WW;
        out[o]          = n00 * inv0;
        out[o + CS]     = n01 * inv0;
        out[o + 2 * CS] = n02 * inv0;
    }
    {
        size_t o = ob + (size_t)gy1 * WW;
        out[o]          = n10 * inv1;
        out[o + CS]     = n11 * inv1;
        out[o + 2 * CS] = n12 * inv1;
    }
}

extern "C" void kernel_launch(void* const* d_in, const int* in_sizes, int n_in,
                              void* d_out, int out_size)
{
    const float* in  = (const float*)d_in[0];
    const float* prm = (const float*)d_in[1];
    float*       out = (float*)d_out;

    const int B = in_sizes[0] / (CH * HH * WW);   // = 4

    cudaFuncSetAttribute(bilateral_kernel,
                         cudaFuncAttributeMaxDynamicSharedMemorySize,
                         (int)SMEM_BYTES);

    dim3 block(TW, 12, 1);                             // 384 threads
    dim3 grid(WW / TW, (HH + TPH - 1) / TPH, B);       // 16 x 22 x 4
    bilateral_kernel<<<grid, block, SMEM_BYTES>>>(in, prm, out);
}